// round 2
// baseline (speedup 1.0000x reference)
#include <cuda_runtime.h>
#include <cstdint>

// Problem constants (from reference setup_inputs)
#define PB 16
#define PL 4096
#define PD 768
#define PS 128
#define D4 (PD / 4)          // 192 float4 per row
#define THREADS D4           // one float4 column per thread
#define NWARPS (THREADS / 32)

// One block per (b, s). Segments are contiguous token ranges (cumsum of
// lengths), so the ragged segment-mean is a fully-coalesced blocked reduction:
// no atomics, no scatter. Each block streams its [start,end) x 768 slice as
// float4, accumulates sum + per-feature nonzero counts, block-reduces the
// total nonzero count (for the degenerate all-zero-segment fallback), then
// writes the mean row (out[b, S+s, :]) and the gathered rep row (out[b, s, :]).
__global__ __launch_bounds__(THREADS) void pooling_kernel(
    const float* __restrict__ wv,            // [B, L, D]
    const int* __restrict__ rep_ids,         // [B, S]
    const int* __restrict__ rep_mask,        // [B, S] bool widened to int32
    const int* __restrict__ lengths,         // [B, S]
    const int* __restrict__ len_mask,        // [B, S] bool widened to int32
    float* __restrict__ out,                 // [B, 2S, D] (+ optional mask tail)
    int write_mask)
{
    const int bs = blockIdx.x;
    const int b = bs >> 7;       // / PS
    const int s = bs & (PS - 1); // % PS
    const int tid = threadIdx.x;

    // --- segment bounds from prefix sum of lengths (uniform, L2-cached) ---
    const int* lrow = lengths + b * PS;
    int start = 0;
#pragma unroll 4
    for (int i = 0; i < s; i++) start += __ldg(&lrow[i]);
    int len = __ldg(&lrow[s]);
    int end = start + len;
    if (start > PL) start = PL;
    if (end > PL) end = PL;

    const float4* __restrict__ wvb =
        reinterpret_cast<const float4*>(wv) + (size_t)b * PL * D4;

    // --- segment sum + per-feature nonzero counts ---
    float4 acc = make_float4(0.f, 0.f, 0.f, 0.f);
    int cx = 0, cy = 0, cz = 0, cw = 0;
    for (int t = start; t < end; t++) {
        float4 v = __ldg(&wvb[(size_t)t * D4 + tid]);
        acc.x += v.x; acc.y += v.y; acc.z += v.z; acc.w += v.w;
        cx += (v.x != 0.f); cy += (v.y != 0.f);
        cz += (v.z != 0.f); cw += (v.w != 0.f);
    }

    // --- block-reduce total nonzero count ---
    int nz = cx + cy + cz + cw;
#pragma unroll
    for (int o = 16; o > 0; o >>= 1)
        nz += __shfl_down_sync(0xffffffffu, nz, o);
    __shared__ int snz[NWARPS];
    if ((tid & 31) == 0) snz[tid >> 5] = nz;
    __syncthreads();
    int total_nz = 0;
#pragma unroll
    for (int w = 0; w < NWARPS; w++) total_nz += snz[w];

    const float mlen = len_mask[b * PS + s] ? 1.f : 0.f;
    const float mrep = rep_mask[b * PS + s] ? 1.f : 0.f;

    float4 mv;
    if (total_nz == 0) {
        // degenerate segment: broadcast word_vectors[0, 0, :]
        mv = __ldg(&reinterpret_cast<const float4*>(wv)[tid]);
    } else {
        mv.x = acc.x / (float)(cx ? cx : 1);
        mv.y = acc.y / (float)(cy ? cy : 1);
        mv.z = acc.z / (float)(cz ? cz : 1);
        mv.w = acc.w / (float)(cw ? cw : 1);
    }
    mv.x *= mlen; mv.y *= mlen; mv.z *= mlen; mv.w *= mlen;

    float4* __restrict__ outb =
        reinterpret_cast<float4*>(out) + (size_t)b * 2 * PS * D4;
    outb[(size_t)(PS + s) * D4 + tid] = mv;

    // --- gather path: sents_rep[b, s, :] = wv[b, rep_ids[b,s], :] * rep_mask ---
    int id = __ldg(&rep_ids[b * PS + s]);
    if (id < 0) id = 0;
    if (id >= PL) id = PL - 1;
    float4 g = __ldg(&wvb[(size_t)id * D4 + tid]);
    g.x *= mrep; g.y *= mrep; g.z *= mrep; g.w *= mrep;
    outb[(size_t)s * D4 + tid] = g;

    // --- mask tail (flattened after [B,2S,D] vector), if present ---
    if (write_mask && tid == 0) {
        float* mo = out + (size_t)PB * 2 * PS * PD;
        mo[b * 2 * PS + s] = mrep;
        mo[b * 2 * PS + PS + s] = mlen;
    }
}

extern "C" void kernel_launch(void* const* d_in, const int* in_sizes, int n_in,
                              void* d_out, int out_size) {
    const float* wv = (const float*)d_in[0];
    const int* rep_ids = (const int*)d_in[1];
    const int* rep_mask = (const int*)d_in[2];
    const int* lengths = (const int*)d_in[3];
    const int* len_mask = (const int*)d_in[4];
    float* out = (float*)d_out;

    const int vec_elems = PB * 2 * PS * PD;
    const int write_mask = (out_size > vec_elems) ? 1 : 0;

    pooling_kernel<<<PB * PS, THREADS>>>(wv, rep_ids, rep_mask, lengths,
                                         len_mask, out, write_mask);
}

// round 5
// speedup vs baseline: 1.1474x; 1.1474x over previous
#include <cuda_runtime.h>
#include <cstdint>

// Problem constants (from reference setup_inputs)
#define PB 16
#define PL 4096
#define PD 768
#define PS 128
#define D4 (PD / 4)          // 192 float4 per row
#define THREADS D4           // one float4 column per thread
#define NWARPS (THREADS / 32)

// Precomputed exclusive segment starts (scratch; device globals are allowed)
__device__ int g_start[PB * PS];

// ---------------------------------------------------------------------------
// Kernel A: per-batch-row exclusive scan of sent_lengths -> g_start.
// 16 blocks x 128 threads, Hillis-Steele in shared memory. Trivial cost.
// ---------------------------------------------------------------------------
__global__ void scan_kernel(const int* __restrict__ lengths) {
    __shared__ int sh[PS];
    const int b = blockIdx.x;
    const int t = threadIdx.x;
    int my = lengths[b * PS + t];
    sh[t] = my;
    __syncthreads();
#pragma unroll
    for (int off = 1; off < PS; off <<= 1) {
        int v = (t >= off) ? sh[t - off] : 0;
        __syncthreads();
        sh[t] += v;
        __syncthreads();
    }
    g_start[b * PS + t] = sh[t] - my;   // exclusive start
}

// ---------------------------------------------------------------------------
// Kernel B: one block per (b, s). Streams the contiguous segment slice with
// unroll-by-4 front-batched float4 loads (MLP>=4/warp), accumulates sum +
// per-feature nonzero counts, block-reduces total nonzero for the degenerate
// fallback, writes mean row + gathered rep row (+ optional mask tail).
// ---------------------------------------------------------------------------
__global__ __launch_bounds__(THREADS) void pooling_kernel(
    const float* __restrict__ wv,            // [B, L, D]
    const int* __restrict__ rep_ids,         // [B, S]
    const int* __restrict__ rep_mask,        // [B, S] bool as int32
    const int* __restrict__ lengths,         // [B, S]
    const int* __restrict__ len_mask,        // [B, S] bool as int32
    float* __restrict__ out,                 // [B, 2S, D] (+ mask tail)
    int write_mask)
{
    const int bs = blockIdx.x;
    const int b = bs >> 7;
    const int s = bs & (PS - 1);
    const int tid = threadIdx.x;

    int start = g_start[bs];
    int len = __ldg(&lengths[bs]);
    int end = start + len;
    if (start > PL) start = PL;
    if (end > PL) end = PL;

    const float4* __restrict__ wvb =
        reinterpret_cast<const float4*>(wv) + (size_t)b * PL * D4;
    const float4* __restrict__ p = wvb + tid;

    // --- segment sum + per-feature nonzero counts, unrolled by 4 ---
    float4 a0 = make_float4(0.f, 0.f, 0.f, 0.f);
    float4 a1 = make_float4(0.f, 0.f, 0.f, 0.f);
    int cx = 0, cy = 0, cz = 0, cw = 0;

    int t = start;
    for (; t + 4 <= end; t += 4) {
        float4 v0 = __ldg(p + (size_t)(t + 0) * D4);
        float4 v1 = __ldg(p + (size_t)(t + 1) * D4);
        float4 v2 = __ldg(p + (size_t)(t + 2) * D4);
        float4 v3 = __ldg(p + (size_t)(t + 3) * D4);
        a0.x += v0.x; a0.y += v0.y; a0.z += v0.z; a0.w += v0.w;
        a1.x += v1.x; a1.y += v1.y; a1.z += v1.z; a1.w += v1.w;
        a0.x += v2.x; a0.y += v2.y; a0.z += v2.z; a0.w += v2.w;
        a1.x += v3.x; a1.y += v3.y; a1.z += v3.z; a1.w += v3.w;
        cx += (v0.x != 0.f) + (v1.x != 0.f) + (v2.x != 0.f) + (v3.x != 0.f);
        cy += (v0.y != 0.f) + (v1.y != 0.f) + (v2.y != 0.f) + (v3.y != 0.f);
        cz += (v0.z != 0.f) + (v1.z != 0.f) + (v2.z != 0.f) + (v3.z != 0.f);
        cw += (v0.w != 0.f) + (v1.w != 0.f) + (v2.w != 0.f) + (v3.w != 0.f);
    }
    for (; t < end; t++) {
        float4 v = __ldg(p + (size_t)t * D4);
        a0.x += v.x; a0.y += v.y; a0.z += v.z; a0.w += v.w;
        cx += (v.x != 0.f); cy += (v.y != 0.f);
        cz += (v.z != 0.f); cw += (v.w != 0.f);
    }
    float4 acc = make_float4(a0.x + a1.x, a0.y + a1.y, a0.z + a1.z, a0.w + a1.w);

    // --- block-reduce total nonzero count ---
    int nz = cx + cy + cz + cw;
#pragma unroll
    for (int o = 16; o > 0; o >>= 1)
        nz += __shfl_down_sync(0xffffffffu, nz, o);
    __shared__ int snz[NWARPS];
    if ((tid & 31) == 0) snz[tid >> 5] = nz;
    __syncthreads();
    int total_nz = 0;
#pragma unroll
    for (int w = 0; w < NWARPS; w++) total_nz += snz[w];

    const float mlen = len_mask[bs] ? 1.f : 0.f;
    const float mrep = rep_mask[bs] ? 1.f : 0.f;

    float4 mv;
    if (total_nz == 0) {
        mv = __ldg(&reinterpret_cast<const float4*>(wv)[tid]);  // wv[0,0,:]
    } else {
        mv.x = acc.x / (float)(cx ? cx : 1);
        mv.y = acc.y / (float)(cy ? cy : 1);
        mv.z = acc.z / (float)(cz ? cz : 1);
        mv.w = acc.w / (float)(cw ? cw : 1);
    }
    mv.x *= mlen; mv.y *= mlen; mv.z *= mlen; mv.w *= mlen;

    float4* __restrict__ outb =
        reinterpret_cast<float4*>(out) + (size_t)b * 2 * PS * D4;
    outb[(size_t)(PS + s) * D4 + tid] = mv;

    // --- gather path ---
    int id = __ldg(&rep_ids[bs]);
    if (id < 0) id = 0;
    if (id >= PL) id = PL - 1;
    float4 g = __ldg(&wvb[(size_t)id * D4 + tid]);
    g.x *= mrep; g.y *= mrep; g.z *= mrep; g.w *= mrep;
    outb[(size_t)s * D4 + tid] = g;

    if (write_mask && tid == 0) {
        float* mo = out + (size_t)PB * 2 * PS * PD;
        mo[b * 2 * PS + s] = mrep;
        mo[b * 2 * PS + PS + s] = mlen;
    }
}

extern "C" void kernel_launch(void* const* d_in, const int* in_sizes, int n_in,
                              void* d_out, int out_size) {
    const float* wv = (const float*)d_in[0];
    const int* rep_ids = (const int*)d_in[1];
    const int* rep_mask = (const int*)d_in[2];
    const int* lengths = (const int*)d_in[3];
    const int* len_mask = (const int*)d_in[4];
    float* out = (float*)d_out;

    const int vec_elems = PB * 2 * PS * PD;
    const int write_mask = (out_size > vec_elems) ? 1 : 0;

    scan_kernel<<<PB, PS>>>(lengths);
    pooling_kernel<<<PB * PS, THREADS>>>(wv, rep_ids, rep_mask, lengths,
                                         len_mask, out, write_mask);
}

// round 6
// speedup vs baseline: 1.1661x; 1.0164x over previous
#include <cuda_runtime.h>
#include <cstdint>

// Problem constants (from reference setup_inputs)
#define PB 16
#define PL 4096
#define PD 768
#define PS 128
#define D4 (PD / 4)          // 192 float4 per row
#define THREADS D4           // one float4 column per thread
#define NWARPS (THREADS / 32)

// Precomputed exclusive segment starts (device-global scratch is allowed)
__device__ int g_start[PB * PS];

// ---------------------------------------------------------------------------
// Kernel A: per-batch-row exclusive scan of sent_lengths -> g_start.
// ---------------------------------------------------------------------------
__global__ void scan_kernel(const int* __restrict__ lengths) {
    __shared__ int sh[PS];
    const int b = blockIdx.x;
    const int t = threadIdx.x;
    int my = lengths[b * PS + t];
    sh[t] = my;
    __syncthreads();
#pragma unroll
    for (int off = 1; off < PS; off <<= 1) {
        int v = (t >= off) ? sh[t - off] : 0;
        __syncthreads();
        sh[t] += v;
        __syncthreads();
    }
    g_start[b * PS + t] = sh[t] - my;   // exclusive start
}

// ---------------------------------------------------------------------------
// Kernel B: one block per (b, s). Token loop unrolled by 8 with front-batched
// float4 loads at immediate offsets (MLP ~8/warp), 32-bit indexing.
// ---------------------------------------------------------------------------
__global__ __launch_bounds__(THREADS) void pooling_kernel(
    const float* __restrict__ wv,            // [B, L, D]
    const int* __restrict__ rep_ids,         // [B, S]
    const int* __restrict__ rep_mask,        // [B, S] bool as int32
    const int* __restrict__ lengths,         // [B, S]
    const int* __restrict__ len_mask,        // [B, S] bool as int32
    float* __restrict__ out,                 // [B, 2S, D] (+ mask tail)
    int write_mask)
{
    const int bs = blockIdx.x;
    const int b = bs >> 7;
    const int s = bs & (PS - 1);
    const int tid = threadIdx.x;

    int start = g_start[bs];
    int len = __ldg(&lengths[bs]);
    int end = start + len;
    if (start > PL) start = PL;
    if (end > PL) end = PL;

    const float4* __restrict__ wvb =
        reinterpret_cast<const float4*>(wv) + (unsigned)b * (PL * D4);

    // Running pointer: one 32-bit add per 8 loads; loads use imm offsets.
    const float4* __restrict__ p = wvb + (unsigned)start * D4 + tid;

    float4 a0 = make_float4(0.f, 0.f, 0.f, 0.f);
    float4 a1 = make_float4(0.f, 0.f, 0.f, 0.f);
    int cx = 0, cy = 0, cz = 0, cw = 0;

    int n = end - start;
    int n8 = n >> 3;
    for (int i = 0; i < n8; i++) {
        float4 v0 = __ldg(p + 0 * D4);
        float4 v1 = __ldg(p + 1 * D4);
        float4 v2 = __ldg(p + 2 * D4);
        float4 v3 = __ldg(p + 3 * D4);
        float4 v4 = __ldg(p + 4 * D4);
        float4 v5 = __ldg(p + 5 * D4);
        float4 v6 = __ldg(p + 6 * D4);
        float4 v7 = __ldg(p + 7 * D4);
        p += 8 * D4;

        a0.x += v0.x; a0.y += v0.y; a0.z += v0.z; a0.w += v0.w;
        a1.x += v1.x; a1.y += v1.y; a1.z += v1.z; a1.w += v1.w;
        a0.x += v2.x; a0.y += v2.y; a0.z += v2.z; a0.w += v2.w;
        a1.x += v3.x; a1.y += v3.y; a1.z += v3.z; a1.w += v3.w;
        a0.x += v4.x; a0.y += v4.y; a0.z += v4.z; a0.w += v4.w;
        a1.x += v5.x; a1.y += v5.y; a1.z += v5.z; a1.w += v5.w;
        a0.x += v6.x; a0.y += v6.y; a0.z += v6.z; a0.w += v6.w;
        a1.x += v7.x; a1.y += v7.y; a1.z += v7.z; a1.w += v7.w;

        cx += (v0.x != 0.f) + (v1.x != 0.f) + (v2.x != 0.f) + (v3.x != 0.f)
            + (v4.x != 0.f) + (v5.x != 0.f) + (v6.x != 0.f) + (v7.x != 0.f);
        cy += (v0.y != 0.f) + (v1.y != 0.f) + (v2.y != 0.f) + (v3.y != 0.f)
            + (v4.y != 0.f) + (v5.y != 0.f) + (v6.y != 0.f) + (v7.y != 0.f);
        cz += (v0.z != 0.f) + (v1.z != 0.f) + (v2.z != 0.f) + (v3.z != 0.f)
            + (v4.z != 0.f) + (v5.z != 0.f) + (v6.z != 0.f) + (v7.z != 0.f);
        cw += (v0.w != 0.f) + (v1.w != 0.f) + (v2.w != 0.f) + (v3.w != 0.f)
            + (v4.w != 0.f) + (v5.w != 0.f) + (v6.w != 0.f) + (v7.w != 0.f);
    }
    for (int r = n & 7; r > 0; r--) {
        float4 v = __ldg(p);
        p += D4;
        a0.x += v.x; a0.y += v.y; a0.z += v.z; a0.w += v.w;
        cx += (v.x != 0.f); cy += (v.y != 0.f);
        cz += (v.z != 0.f); cw += (v.w != 0.f);
    }
    float4 acc = make_float4(a0.x + a1.x, a0.y + a1.y, a0.z + a1.z, a0.w + a1.w);

    // --- block-reduce total nonzero count ---
    int nz = cx + cy + cz + cw;
#pragma unroll
    for (int o = 16; o > 0; o >>= 1)
        nz += __shfl_down_sync(0xffffffffu, nz, o);
    __shared__ int snz[NWARPS];
    if ((tid & 31) == 0) snz[tid >> 5] = nz;
    __syncthreads();
    int total_nz = 0;
#pragma unroll
    for (int w = 0; w < NWARPS; w++) total_nz += snz[w];

    const float mlen = len_mask[bs] ? 1.f : 0.f;
    const float mrep = rep_mask[bs] ? 1.f : 0.f;

    float4 mv;
    if (total_nz == 0) {
        mv = __ldg(&reinterpret_cast<const float4*>(wv)[tid]);  // wv[0,0,:]
    } else {
        mv.x = acc.x / (float)(cx ? cx : 1);
        mv.y = acc.y / (float)(cy ? cy : 1);
        mv.z = acc.z / (float)(cz ? cz : 1);
        mv.w = acc.w / (float)(cw ? cw : 1);
    }
    mv.x *= mlen; mv.y *= mlen; mv.z *= mlen; mv.w *= mlen;

    float4* __restrict__ outb =
        reinterpret_cast<float4*>(out) + (unsigned)b * (2 * PS * D4);
    outb[(unsigned)(PS + s) * D4 + tid] = mv;

    // --- gather path ---
    int id = __ldg(&rep_ids[bs]);
    if (id < 0) id = 0;
    if (id >= PL) id = PL - 1;
    float4 g = __ldg(&wvb[(unsigned)id * D4 + tid]);
    g.x *= mrep; g.y *= mrep; g.z *= mrep; g.w *= mrep;
    outb[(unsigned)s * D4 + tid] = g;

    if (write_mask && tid == 0) {
        float* mo = out + (size_t)PB * 2 * PS * PD;
        mo[b * 2 * PS + s] = mrep;
        mo[b * 2 * PS + PS + s] = mlen;
    }
}

extern "C" void kernel_launch(void* const* d_in, const int* in_sizes, int n_in,
                              void* d_out, int out_size) {
    const float* wv = (const float*)d_in[0];
    const int* rep_ids = (const int*)d_in[1];
    const int* rep_mask = (const int*)d_in[2];
    const int* lengths = (const int*)d_in[3];
    const int* len_mask = (const int*)d_in[4];
    float* out = (float*)d_out;

    const int vec_elems = PB * 2 * PS * PD;
    const int write_mask = (out_size > vec_elems) ? 1 : 0;

    scan_kernel<<<PB, PS>>>(lengths);
    pooling_kernel<<<PB * PS, THREADS>>>(wv, rep_ids, rep_mask, lengths,
                                         len_mask, out, write_mask);
}